// round 5
// baseline (speedup 1.0000x reference)
#include <cuda_runtime.h>
#include <cuda_bf16.h>
#include <math.h>
#include <cstdint>

#define TT 64
#define BB 128
#define NN 2048

#define C_ELEMS 1024                       // elements per CTA chunk
#define GRID    (BB * NN / C_ELEMS)        // 256 CTAs
#define THREADS 128
#define EPT     (C_ELEMS / THREADS)        // 8 elements per thread
#define S_STAGES 6
#define TILE_BYTES (C_ELEMS * 4)           // 4096 B per x tile

// Precomputed scratch (allocation-free: __device__ globals)
__device__ __align__(16) float g_W[TT * NN];     // 1 - beta*(1 - sigmoid(cond))
__device__ __align__(16) float g_decay[NN];
__device__ __align__(16) float g_decayg[NN];
__device__ __align__(16) float g_leak[NN];
__device__ __align__(16) float g_rst[NN];
__device__ __align__(16) float g_vth[NN];

__device__ __forceinline__ float sigm_fast(float x) {
    return 1.0f / (1.0f + __expf(-x));
}

// ---------------- prep ----------------
__global__ void __launch_bounds__(256)
glif_prep(const float* __restrict__ alpha,
          const float* __restrict__ beta,
          const float* __restrict__ gamma,
          const float* __restrict__ tau,
          const float* __restrict__ Vth,
          const float* __restrict__ leak,
          const float* __restrict__ reVth,
          const float* __restrict__ cond) {
    int i4 = blockIdx.x * blockDim.x + threadIdx.x;   // over T*N/4
    if (i4 >= TT * NN / 4) return;
    int n4 = i4 & (NN / 4 - 1);

    const float4 c  = reinterpret_cast<const float4*>(cond)[i4];
    const float4 bt = reinterpret_cast<const float4*>(beta)[n4];
    float4 w;
    w.x = 1.0f - sigm_fast(bt.x) * (1.0f - sigm_fast(c.x));
    w.y = 1.0f - sigm_fast(bt.y) * (1.0f - sigm_fast(c.y));
    w.z = 1.0f - sigm_fast(bt.z) * (1.0f - sigm_fast(c.z));
    w.w = 1.0f - sigm_fast(bt.w) * (1.0f - sigm_fast(c.w));
    reinterpret_cast<float4*>(g_W)[i4] = w;

    if (i4 < NN / 4) {
        const float4 av = reinterpret_cast<const float4*>(alpha)[i4];
        const float4 gv = reinterpret_cast<const float4*>(gamma)[i4];
        const float4 tv = reinterpret_cast<const float4*>(tau)[i4];
        const float4 vv = reinterpret_cast<const float4*>(Vth)[i4];
        const float4 lv = reinterpret_cast<const float4*>(leak)[i4];
        const float4 rv = reinterpret_cast<const float4*>(reVth)[i4];
        float4 dec, decg, lk, rs, vt;
        {
            float al = sigm_fast(av.x), ga = sigm_fast(gv.x);
            float d = 1.0f - al * (1.0f - sigm_fast(tv.x));
            dec.x = d; decg.x = d * (1.0f - ga);
            lk.x = (1.0f - al) * sigm_fast(lv.x);
            rs.x = (1.0f - ga) * sigm_fast(rv.x);
            vt.x = sigm_fast(vv.x);
        }
        {
            float al = sigm_fast(av.y), ga = sigm_fast(gv.y);
            float d = 1.0f - al * (1.0f - sigm_fast(tv.y));
            dec.y = d; decg.y = d * (1.0f - ga);
            lk.y = (1.0f - al) * sigm_fast(lv.y);
            rs.y = (1.0f - ga) * sigm_fast(rv.y);
            vt.y = sigm_fast(vv.y);
        }
        {
            float al = sigm_fast(av.z), ga = sigm_fast(gv.z);
            float d = 1.0f - al * (1.0f - sigm_fast(tv.z));
            dec.z = d; decg.z = d * (1.0f - ga);
            lk.z = (1.0f - al) * sigm_fast(lv.z);
            rs.z = (1.0f - ga) * sigm_fast(rv.z);
            vt.z = sigm_fast(vv.z);
        }
        {
            float al = sigm_fast(av.w), ga = sigm_fast(gv.w);
            float d = 1.0f - al * (1.0f - sigm_fast(tv.w));
            dec.w = d; decg.w = d * (1.0f - ga);
            lk.w = (1.0f - al) * sigm_fast(lv.w);
            rs.w = (1.0f - ga) * sigm_fast(rv.w);
            vt.w = sigm_fast(vv.w);
        }
        reinterpret_cast<float4*>(g_decay)[i4]  = dec;
        reinterpret_cast<float4*>(g_decayg)[i4] = decg;
        reinterpret_cast<float4*>(g_leak)[i4]   = lk;
        reinterpret_cast<float4*>(g_rst)[i4]    = rs;
        reinterpret_cast<float4*>(g_vth)[i4]    = vt;
    }
}

// ---------------- bulk-async helpers ----------------
__device__ __forceinline__ uint32_t smem_u32(const void* p) {
    return (uint32_t)__cvta_generic_to_shared(p);
}

__device__ __forceinline__ void mbar_init(uint32_t mbar, uint32_t cnt) {
    asm volatile("mbarrier.init.shared.b64 [%0], %1;" :: "r"(mbar), "r"(cnt) : "memory");
}

__device__ __forceinline__ void mbar_expect_tx(uint32_t mbar, uint32_t bytes) {
    asm volatile("mbarrier.arrive.expect_tx.shared.b64 _, [%0], %1;"
                 :: "r"(mbar), "r"(bytes) : "memory");
}

__device__ __forceinline__ void mbar_wait(uint32_t mbar, uint32_t phase) {
    asm volatile(
        "{\n\t"
        ".reg .pred P1;\n\t"
        "WAIT_LOOP_%=:\n\t"
        "mbarrier.try_wait.parity.acquire.cta.shared::cta.b64 P1, [%0], %1, 0x989680;\n\t"
        "@P1 bra.uni WAIT_DONE_%=;\n\t"
        "bra.uni WAIT_LOOP_%=;\n\t"
        "WAIT_DONE_%=:\n\t"
        "}"
        :: "r"(mbar), "r"(phase) : "memory");
}

__device__ __forceinline__ void bulk_load(uint32_t smem_dst, const void* gmem_src,
                                          uint32_t bytes, uint32_t mbar) {
    asm volatile(
        "cp.async.bulk.shared::cta.global.mbarrier::complete_tx::bytes [%0], [%1], %2, [%3];"
        :: "r"(smem_dst), "l"(gmem_src), "r"(bytes), "r"(mbar) : "memory");
}

__device__ __forceinline__ void bulk_store(void* gmem_dst, uint32_t smem_src, uint32_t bytes) {
    asm volatile(
        "cp.async.bulk.global.shared::cta.bulk_group [%0], [%1], %2;"
        :: "l"(gmem_dst), "r"(smem_src), "r"(bytes) : "memory");
}

__device__ __forceinline__ void bulk_commit() {
    asm volatile("cp.async.bulk.commit_group;" ::: "memory");
}

template <int N_>
__device__ __forceinline__ void bulk_wait_read() {
    asm volatile("cp.async.bulk.wait_group.read %0;" :: "n"(N_) : "memory");
}

__device__ __forceinline__ void fence_async_smem() {
    asm volatile("fence.proxy.async.shared::cta;" ::: "memory");
}

// ---------------- main scan: bulk-async pipelined ----------------
__global__ void __launch_bounds__(THREADS)
glif_main(const float* __restrict__ tx, float* __restrict__ out) {
    __shared__ __align__(16) float sx[S_STAGES][C_ELEMS];   // x tiles
    __shared__ __align__(16) float so[2][C_ELEMS];          // out tiles
    __shared__ __align__(8)  uint64_t mbar_full[S_STAGES];

    const int tid   = threadIdx.x;
    const int base  = blockIdx.x * C_ELEMS;         // element offset within (B*N)
    const int n_base = base & (NN - 1);             // aligned since C_ELEMS | NN
    const int stride = BB * NN;                     // per-timestep element stride

    uint32_t mb[S_STAGES];
    #pragma unroll
    for (int s = 0; s < S_STAGES; ++s) mb[s] = smem_u32(&mbar_full[s]);

    if (tid == 0) {
        #pragma unroll
        for (int s = 0; s < S_STAGES; ++s) mbar_init(mb[s], 1);
    }
    __syncthreads();

    // Prologue: issue loads for t = 0..S-1
    if (tid == 0) {
        #pragma unroll
        for (int s = 0; s < S_STAGES; ++s) {
            mbar_expect_tx(mb[s], TILE_BYTES);
            bulk_load(smem_u32(&sx[s][0]), tx + (size_t)s * stride + base,
                      TILE_BYTES, mb[s]);
        }
    }

    // Per-thread neuron params (strided: n = n_base + tid + k*THREADS)
    float dec[EPT], dd[EPT], lk[EPT], rs[EPT], vth[EPT];
    float v[EPT], y[EPT], wc[EPT], wn[EPT];
    #pragma unroll
    for (int k = 0; k < EPT; ++k) {
        int n = n_base + tid + k * THREADS;
        float d  = g_decay[n];
        float dg = g_decayg[n];
        dec[k] = d;
        dd[k]  = dg - d;
        lk[k]  = g_leak[n];
        rs[k]  = g_rst[n];
        vth[k] = g_vth[n];
        v[k] = 0.f;
        y[k] = 0.f;
        wc[k] = __ldg(&g_W[n]);            // W for t=0
    }

    int st = 0;
    uint32_t ph = 0;

    #pragma unroll 1
    for (int t = 0; t < TT; ++t) {
        // Prefetch W for t+1 (L2-resident) before touching dependency chain
        if (t + 1 < TT) {
            #pragma unroll
            for (int k = 0; k < EPT; ++k)
                wn[k] = __ldg(&g_W[(t + 1) * NN + n_base + tid + k * THREADS]);
        }

        // x tile for step t ready?
        mbar_wait(mb[st], ph);

        // out buffer (t&1) free? (bulk store from step t-2 must have read it)
        if (tid == 0 && t >= 2) bulk_wait_read<1>();
        __syncthreads();

        const float* xs = &sx[st][0];
        float* os = &so[t & 1][0];
        #pragma unroll
        for (int k = 0; k < EPT; ++k) {
            float x  = xs[tid + k * THREADS];
            float dv = fmaf(y[k], dd[k], dec[k]);
            float c  = fmaf(y[k], -rs[k], fmaf(x, wc[k], -lk[k]));
            v[k] = fmaf(dv, v[k], c);
            y[k] = (v[k] > vth[k]) ? 1.0f : 0.0f;
            os[tid + k * THREADS] = y[k];
            wc[k] = wn[k];
        }

        __syncthreads();   // STS to `os` visible; x tile fully consumed

        if (tid == 0) {
            fence_async_smem();
            bulk_store(out + (size_t)t * stride + base, smem_u32(os), TILE_BYTES);
            bulk_commit();
            if (t + S_STAGES < TT) {
                mbar_expect_tx(mb[st], TILE_BYTES);
                bulk_load(smem_u32(&sx[st][0]),
                          tx + (size_t)(t + S_STAGES) * stride + base,
                          TILE_BYTES, mb[st]);
            }
        }

        if (++st == S_STAGES) { st = 0; ph ^= 1; }
    }

    // Drain outstanding bulk stores before CTA exit
    if (tid == 0) bulk_wait_read<0>();
}

extern "C" void kernel_launch(void* const* d_in, const int* in_sizes, int n_in,
                              void* d_out, int out_size) {
    // metadata order: tx, alpha, beta, gamma, tau, Vth, leak, reVth, conduct
    const float* tx    = (const float*)d_in[0];
    const float* alpha = (const float*)d_in[1];
    const float* beta  = (const float*)d_in[2];
    const float* gamma = (const float*)d_in[3];
    const float* tau   = (const float*)d_in[4];
    const float* Vth   = (const float*)d_in[5];
    const float* leak  = (const float*)d_in[6];
    const float* reVth = (const float*)d_in[7];
    const float* cond  = (const float*)d_in[8];
    float* out = (float*)d_out;

    {
        int total = TT * NN / 4;   // 32768 threads
        int blk = 256;
        glif_prep<<<(total + blk - 1) / blk, blk>>>(alpha, beta, gamma, tau,
                                                    Vth, leak, reVth, cond);
    }
    glif_main<<<GRID, THREADS>>>(tx, out);
}

// round 6
// speedup vs baseline: 1.4512x; 1.4512x over previous
#include <cuda_runtime.h>
#include <cuda_bf16.h>
#include <math.h>

#define TT 64
#define BB 128
#define NN 2048

// Precomputed scratch (allocation-free: __device__ globals)
__device__ __align__(16) float g_W[TT * NN];     // 1 - beta*(1 - sigmoid(cond))  [T,N]
__device__ __align__(16) float g_decay[NN];      // 1 - al*(1-tau_s)
__device__ __align__(16) float g_decayg[NN];     // decay * (1-ga)
__device__ __align__(16) float g_leak[NN];       // (1-al)*leak_s
__device__ __align__(16) float g_rst[NN];        // (1-ga)*reVth_s
__device__ __align__(16) float g_vth[NN];        // sigmoid(Vth)

__device__ __forceinline__ float sigm_fast(float x) {
    return 1.0f / (1.0f + __expf(-x));
}

// Vectorized prep: one thread per 4 (t,n) cells of W.
// Triggers programmatic launch of glif_main immediately so the main kernel's
// launch + prep-independent tx prefetches overlap with this kernel.
__global__ void __launch_bounds__(256)
glif_prep(const float* __restrict__ alpha,
          const float* __restrict__ beta,
          const float* __restrict__ gamma,
          const float* __restrict__ tau,
          const float* __restrict__ Vth,
          const float* __restrict__ leak,
          const float* __restrict__ reVth,
          const float* __restrict__ cond) {
    cudaTriggerProgrammaticLaunchCompletion();

    int i4 = blockIdx.x * blockDim.x + threadIdx.x;   // over T*N/4
    if (i4 >= TT * NN / 4) return;
    int n4 = i4 & (NN / 4 - 1);                       // float4 index within N

    const float4 c  = reinterpret_cast<const float4*>(cond)[i4];
    const float4 bt = reinterpret_cast<const float4*>(beta)[n4];
    float4 w;
    w.x = 1.0f - sigm_fast(bt.x) * (1.0f - sigm_fast(c.x));
    w.y = 1.0f - sigm_fast(bt.y) * (1.0f - sigm_fast(c.y));
    w.z = 1.0f - sigm_fast(bt.z) * (1.0f - sigm_fast(c.z));
    w.w = 1.0f - sigm_fast(bt.w) * (1.0f - sigm_fast(c.w));
    reinterpret_cast<float4*>(g_W)[i4] = w;

    if (i4 < NN / 4) {
        const float4 av = reinterpret_cast<const float4*>(alpha)[i4];
        const float4 gv = reinterpret_cast<const float4*>(gamma)[i4];
        const float4 tv = reinterpret_cast<const float4*>(tau)[i4];
        const float4 vv = reinterpret_cast<const float4*>(Vth)[i4];
        const float4 lv = reinterpret_cast<const float4*>(leak)[i4];
        const float4 rv = reinterpret_cast<const float4*>(reVth)[i4];
        float4 dec, decg, lk, rs, vt;
        {
            float al = sigm_fast(av.x), ga = sigm_fast(gv.x);
            float d = 1.0f - al * (1.0f - sigm_fast(tv.x));
            dec.x = d; decg.x = d * (1.0f - ga);
            lk.x = (1.0f - al) * sigm_fast(lv.x);
            rs.x = (1.0f - ga) * sigm_fast(rv.x);
            vt.x = sigm_fast(vv.x);
        }
        {
            float al = sigm_fast(av.y), ga = sigm_fast(gv.y);
            float d = 1.0f - al * (1.0f - sigm_fast(tv.y));
            dec.y = d; decg.y = d * (1.0f - ga);
            lk.y = (1.0f - al) * sigm_fast(lv.y);
            rs.y = (1.0f - ga) * sigm_fast(rv.y);
            vt.y = sigm_fast(vv.y);
        }
        {
            float al = sigm_fast(av.z), ga = sigm_fast(gv.z);
            float d = 1.0f - al * (1.0f - sigm_fast(tv.z));
            dec.z = d; decg.z = d * (1.0f - ga);
            lk.z = (1.0f - al) * sigm_fast(lv.z);
            rs.z = (1.0f - ga) * sigm_fast(rv.z);
            vt.z = sigm_fast(vv.z);
        }
        {
            float al = sigm_fast(av.w), ga = sigm_fast(gv.w);
            float d = 1.0f - al * (1.0f - sigm_fast(tv.w));
            dec.w = d; decg.w = d * (1.0f - ga);
            lk.w = (1.0f - al) * sigm_fast(lv.w);
            rs.w = (1.0f - ga) * sigm_fast(rv.w);
            vt.w = sigm_fast(vv.w);
        }
        reinterpret_cast<float4*>(g_decay)[i4]  = dec;
        reinterpret_cast<float4*>(g_decayg)[i4] = decg;
        reinterpret_cast<float4*>(g_leak)[i4]   = lk;
        reinterpret_cast<float4*>(g_rst)[i4]    = rs;
        reinterpret_cast<float4*>(g_vth)[i4]    = vt;
    }
}

// Main scan: one thread owns 2 consecutive neurons for one batch row,
// carries (v,y) in registers across T=64 steps. Prefetch depth 1.
// PDL: issues prep-independent tx loads BEFORE cudaGridDependencySynchronize().
__global__ void __launch_bounds__(128)
glif_main(const float* __restrict__ tx, float* __restrict__ out) {
    const int tid = blockIdx.x * blockDim.x + threadIdx.x;  // 0 .. B*N/2-1
    const int n2  = tid & (NN / 2 - 1);                     // float2 group within N

    const float2* __restrict__ tx2 = reinterpret_cast<const float2*>(tx);
    const float2* __restrict__ W2  = reinterpret_cast<const float2*>(g_W);
    float2* __restrict__ out2      = reinterpret_cast<float2*>(out);

    const int stride = BB * NN / 2;   // float2 stride per timestep
    const int wstr   = NN / 2;

    // Prep-independent: start streaming tx for t=0 (and t=1) right away,
    // overlapping with glif_prep still running.
    float2 x  = __ldcs(&tx2[tid]);
    float2 x1 = __ldcs(&tx2[stride + tid]);

    // Wait for glif_prep's writes to g_W / g_* to be visible.
    cudaGridDependencySynchronize();

    const float2 dec  = reinterpret_cast<const float2*>(g_decay)[n2];
    const float2 decg = reinterpret_cast<const float2*>(g_decayg)[n2];
    const float2 lk   = reinterpret_cast<const float2*>(g_leak)[n2];
    const float2 rs   = reinterpret_cast<const float2*>(g_rst)[n2];
    const float2 vth  = reinterpret_cast<const float2*>(g_vth)[n2];

    const float ddx = decg.x - dec.x;   // dv = fma(y, ddx, dec)
    const float ddy = decg.y - dec.y;

    float2 v = make_float2(0.f, 0.f);
    float2 y = make_float2(0.f, 0.f);

    float2 w = __ldg(&W2[n2]);   // W for t=0

    // t = 0 (uses x, w; x1 already in flight)
    {
        float c = fmaf(y.x, -rs.x, fmaf(x.x, w.x, -lk.x));
        v.x = fmaf(dec.x, v.x, c);
        y.x = (v.x > vth.x) ? 1.0f : 0.0f;
        c = fmaf(y.y, -rs.y, fmaf(x.y, w.y, -lk.y));
        v.y = fmaf(dec.y, v.y, c);
        y.y = (v.y > vth.y) ? 1.0f : 0.0f;
        __stcs(&out2[tid], y);
    }

    x = x1;
    w = __ldg(&W2[wstr + n2]);   // W for t=1

    #pragma unroll 8
    for (int t = 1; t < TT; ++t) {
        // Prefetch t+1 before touching the dependency chain
        float2 xn, wn;
        if (t + 1 < TT) {
            xn = __ldcs(&tx2[(t + 1) * stride + tid]);
            wn = __ldg(&W2[(t + 1) * wstr + n2]);
        }

        // lane 0
        {
            float dv = fmaf(y.x, ddx, dec.x);
            float c  = fmaf(y.x, -rs.x, fmaf(x.x, w.x, -lk.x));
            v.x = fmaf(dv, v.x, c);
            y.x = (v.x > vth.x) ? 1.0f : 0.0f;
        }
        // lane 1
        {
            float dv = fmaf(y.y, ddy, dec.y);
            float c  = fmaf(y.y, -rs.y, fmaf(x.y, w.y, -lk.y));
            v.y = fmaf(dv, v.y, c);
            y.y = (v.y > vth.y) ? 1.0f : 0.0f;
        }

        __stcs(&out2[t * stride + tid], y);
        x = xn;
        w = wn;
    }
}

extern "C" void kernel_launch(void* const* d_in, const int* in_sizes, int n_in,
                              void* d_out, int out_size) {
    // metadata order: tx, alpha, beta, gamma, tau, Vth, leak, reVth, conduct
    const float* tx    = (const float*)d_in[0];
    const float* alpha = (const float*)d_in[1];
    const float* beta  = (const float*)d_in[2];
    const float* gamma = (const float*)d_in[3];
    const float* tau   = (const float*)d_in[4];
    const float* Vth   = (const float*)d_in[5];
    const float* leak  = (const float*)d_in[6];
    const float* reVth = (const float*)d_in[7];
    const float* cond  = (const float*)d_in[8];
    float* out = (float*)d_out;

    // Kernel 1: prep (triggers programmatic launch completion at entry)
    {
        int total = TT * NN / 4;   // 32768 threads
        int blk = 256;
        glif_prep<<<(total + blk - 1) / blk, blk>>>(alpha, beta, gamma, tau,
                                                    Vth, leak, reVth, cond);
    }

    // Kernel 2: main, launched with Programmatic Stream Serialization so it
    // begins (launch + prep-independent tx loads) while prep is still running.
    {
        cudaLaunchConfig_t cfg = {};
        cfg.gridDim  = dim3(BB * NN / 2 / 128, 1, 1);   // 1024 blocks
        cfg.blockDim = dim3(128, 1, 1);
        cfg.dynamicSmemBytes = 0;
        cfg.stream = 0;
        cudaLaunchAttribute attr[1];
        attr[0].id = cudaLaunchAttributeProgrammaticStreamSerialization;
        attr[0].val.programmaticStreamSerializationAllowed = 1;
        cfg.attrs = attr;
        cfg.numAttrs = 1;
        cudaLaunchKernelEx(&cfg, glif_main, tx, out);
    }
}